// round 7
// baseline (speedup 1.0000x reference)
#include <cuda_runtime.h>
#include <math.h>
#include <stdint.h>

// Problem constants (fixed by setup_inputs)
#define BATCH   2
#define IMG     224
#define TOKENS  (BATCH*IMG*IMG)   // 100352
#define DIM     768
#define NH      12
#define HD      64
#define WS      7
#define L       (WS*WS)           // 49
#define NWIN    (BATCH*(IMG/WS)*(IMG/WS))  // 2048
#define SHIFT   3

// Scratch (device globals: allocation is forbidden in kernel_launch)
__device__ float    g_qkv[(size_t)TOKENS * 3 * DIM];
__device__ uint16_t g_xhi[(size_t)TOKENS * DIM];
__device__ uint16_t g_xlo[(size_t)TOKENS * DIM];
__device__ uint16_t g_qwhi[(size_t)3 * DIM * DIM];
__device__ uint16_t g_qwlo[(size_t)3 * DIM * DIM];
__device__ uint16_t g_pwhi[(size_t)DIM * DIM];
__device__ uint16_t g_pwlo[(size_t)DIM * DIM];
__device__ uint16_t g_atthi[(size_t)TOKENS * DIM];
__device__ uint16_t g_attlo[(size_t)TOKENS * DIM];
__device__ float    g_sin[L * 32];
__device__ float    g_cos[L * 32];

// ============================================================================
// helpers
// ============================================================================
__device__ __forceinline__ uint32_t smem_u32(const void* p) {
    uint32_t a;
    asm("{ .reg .u64 t; cvta.to.shared.u64 t, %1; cvt.u32.u64 %0, t; }" : "=r"(a) : "l"(p));
    return a;
}

// pack two fp32 -> bf16x2 (low 16 bits = x, high = y), plus residual pair
__device__ __forceinline__ void split_pack(float x, float y, uint32_t& hi, uint32_t& lo) {
    asm("cvt.rn.bf16x2.f32 %0, %1, %2;" : "=r"(hi) : "f"(y), "f"(x));
    float hx = __uint_as_float(hi << 16);
    float hy = __uint_as_float(hi & 0xffff0000u);
    float lx = x - hx;
    float ly = y - hy;
    asm("cvt.rn.bf16x2.f32 %0, %1, %2;" : "=r"(lo) : "f"(ly), "f"(lx));
}

// single fp32 -> bf16 hi + bf16 residual
__device__ __forceinline__ void split1(float x, uint16_t& h, uint16_t& l) {
    uint16_t hh;
    asm("cvt.rn.bf16.f32 %0, %1;" : "=h"(hh) : "f"(x));
    float hf = __uint_as_float(((uint32_t)hh) << 16);
    asm("cvt.rn.bf16.f32 %0, %1;" : "=h"(l) : "f"(x - hf));
    h = hh;
}

// ---- packed f32x2 (Blackwell FFMA2) ----
__device__ __forceinline__ unsigned long long pk2(float x, float y) {
    unsigned long long r;
    asm("mov.b64 %0, {%1,%2};" : "=l"(r) : "f"(x), "f"(y));
    return r;
}
__device__ __forceinline__ void fma2(unsigned long long& d,
                                     unsigned long long a, unsigned long long b) {
    asm("fma.rn.f32x2 %0, %1, %2, %0;" : "+l"(d) : "l"(a), "l"(b));
}
__device__ __forceinline__ float2 upk2(unsigned long long v) {
    float x, y;
    asm("mov.b64 {%0,%1}, %2;" : "=f"(x), "=f"(y) : "l"(v));
    return make_float2(x, y);
}

#define CPA16(dst, src) \
    asm volatile("cp.async.cg.shared.global [%0], [%1], 16;" :: "r"(dst), "l"(src) : "memory")
#define CPA_COMMIT() asm volatile("cp.async.commit_group;" ::: "memory")
#define CPA_WAIT2()  asm volatile("cp.async.wait_group 2;" ::: "memory")

#define LDSM4(r, addr) \
    asm volatile("ldmatrix.sync.aligned.m8n8.x4.shared.b16 {%0,%1,%2,%3}, [%4];" \
        : "=r"((r)[0]), "=r"((r)[1]), "=r"((r)[2]), "=r"((r)[3]) : "r"(addr))

#define MMA16816(d, a, b0, b1) \
    asm volatile("mma.sync.aligned.m16n8k16.row.col.f32.bf16.bf16.f32 " \
        "{%0,%1,%2,%3},{%4,%5,%6,%7},{%8,%9},{%0,%1,%2,%3};" \
        : "+f"((d)[0]), "+f"((d)[1]), "+f"((d)[2]), "+f"((d)[3]) \
        : "r"((a)[0]), "r"((a)[1]), "r"((a)[2]), "r"((a)[3]), "r"(b0), "r"(b1))

// ============================================================================
// RoPE tables
// ============================================================================
__global__ void rope_init_kernel() {
    for (int i = threadIdx.x; i < L * 32; i += blockDim.x) {
        int tok = i >> 5, d = i & 31;
        int ty = tok / WS, tx = tok - ty * WS;
        int f = d & 15;
        float inv = powf(100.0f, -((float)f) / 16.0f);
        float ang = ((d < 16) ? (float)ty : (float)tx) * inv;
        g_sin[i] = sinf(ang);
        g_cos[i] = cosf(ang);
    }
}

// ============================================================================
// fp32 -> bf16 hi/lo split pre-pass (vectorized, grid-stride)
// ============================================================================
__global__ void split_kernel(const float* __restrict__ src,
                             uint16_t* __restrict__ hi, uint16_t* __restrict__ lo,
                             size_t n4)
{
    size_t idx = (size_t)blockIdx.x * blockDim.x + threadIdx.x;
    size_t stride = (size_t)gridDim.x * blockDim.x;
    for (; idx < n4; idx += stride) {
        float4 v = ((const float4*)src)[idx];
        uint32_t h0, l0, h1, l1;
        split_pack(v.x, v.y, h0, l0);
        split_pack(v.z, v.w, h1, l1);
        ((uint2*)hi)[idx] = make_uint2(h0, h1);
        ((uint2*)lo)[idx] = make_uint2(l0, l1);
    }
}

// ============================================================================
// 3x-BF16-split GEMM, pre-split bf16 hi/lo operands, cp.async 4-stage:
//   C[M,N] = A[M,K] @ W[N,K]^T  (fp32 out)
// CTA tile 128x256, BK=16, 256 threads (8 warps, 2x4, warp tile 64x64).
// ============================================================================
#define BM 128
#define BN 256
#define BK 16
#define PADB 48
#define A_LO  6144u
#define B_HI  12288u
#define B_LO  24576u
#define BUF_B 36864u
#define STAGES 4
#define SMEM_GEMM (STAGES * BUF_B)   // 147456

__global__ __launch_bounds__(256, 1) void gemm_presplit_kernel(
    const uint16_t* __restrict__ Ahi, const uint16_t* __restrict__ Alo,
    const uint16_t* __restrict__ Bhi, const uint16_t* __restrict__ Blo,
    float* __restrict__ C, int M, int N, int K)
{
    extern __shared__ char smem[];
    const uint32_t sb = smem_u32(smem);
    const int tid  = threadIdx.x;
    const int lane = tid & 31;
    const int wid  = tid >> 5;
    const int mtile = blockIdx.y, ntile = blockIdx.x;
    const int rm = (wid & 1) * 64;
    const int nb = (wid >> 1) * 64;

    const int arow = tid >> 1, ahalf = tid & 1;
    const uint16_t* pAhi = Ahi + (size_t)(mtile * BM + arow) * K + ahalf * 8;
    const uint16_t* pAlo = Alo + (size_t)(mtile * BM + arow) * K + ahalf * 8;
    const uint16_t* pBhi = Bhi + (size_t)(ntile * BN + arow) * K + ahalf * 8;
    const uint16_t* pBlo = Blo + (size_t)(ntile * BN + arow) * K + ahalf * 8;
    const size_t bstep = (size_t)128 * K;

    const uint32_t dA = sb + (uint32_t)(arow * PADB + ahalf * 16);
    const uint32_t dB = sb + B_HI + (uint32_t)(arow * PADB + ahalf * 16);

    auto issue = [&](int s) {
        const uint32_t off = (uint32_t)(s & 3) * BUF_B;
        const int k0 = s * BK;
        CPA16(dA + off,                               pAhi + k0);
        CPA16(dA + off + A_LO,                        pAlo + k0);
        CPA16(dB + off,                               pBhi + k0);
        CPA16(dB + off + 128u * PADB,                 pBhi + bstep + k0);
        CPA16(dB + off + (B_LO - B_HI),               pBlo + k0);
        CPA16(dB + off + (B_LO - B_HI) + 128u * PADB, pBlo + bstep + k0);
        CPA_COMMIT();
    };

    float acc[4][8][4];
#pragma unroll
    for (int mt = 0; mt < 4; ++mt)
#pragma unroll
        for (int nt = 0; nt < 8; ++nt)
#pragma unroll
            for (int e = 0; e < 4; ++e) acc[mt][nt][e] = 0.0f;

    const uint32_t a_l = sb + (uint32_t)((rm + (lane & 15)) * PADB + (lane >> 4) * 16);
    const uint32_t b_l = sb + B_HI + (uint32_t)((nb + (lane & 7) + ((lane >> 4) << 3)) * PADB
                                                + ((lane >> 3) & 1) * 16);

    const int NIT = K / BK;   // 48
    issue(0); issue(1); issue(2);

    for (int it = 0; it < NIT; ++it) {
        CPA_WAIT2();
        __syncthreads();
        const uint32_t so = (uint32_t)(it & 3) * BUF_B;

        uint32_t ah[4][4], al[4][4];
#pragma unroll
        for (int mt = 0; mt < 4; ++mt) {
            LDSM4(ah[mt], a_l + so + mt * (16 * PADB));
            LDSM4(al[mt], a_l + so + A_LO + mt * (16 * PADB));
        }

#pragma unroll
        for (int half = 0; half < 2; ++half) {
            uint32_t bh[2][4], bl[2][4];
#pragma unroll
            for (int q = 0; q < 2; ++q) {
                const int nt2 = half * 2 + q;
                LDSM4(bh[q], b_l + so + nt2 * (16 * PADB));
                LDSM4(bl[q], b_l + so + (B_LO - B_HI) + nt2 * (16 * PADB));
            }
#pragma unroll
            for (int mt = 0; mt < 4; ++mt)
#pragma unroll
                for (int q = 0; q < 2; ++q) {
                    MMA16816(acc[mt][half * 4 + 2 * q],     ah[mt], bh[q][0], bh[q][1]);
                    MMA16816(acc[mt][half * 4 + 2 * q + 1], ah[mt], bh[q][2], bh[q][3]);
                }
#pragma unroll
            for (int mt = 0; mt < 4; ++mt)
#pragma unroll
                for (int q = 0; q < 2; ++q) {
                    MMA16816(acc[mt][half * 4 + 2 * q],     ah[mt], bl[q][0], bl[q][1]);
                    MMA16816(acc[mt][half * 4 + 2 * q + 1], ah[mt], bl[q][2], bl[q][3]);
                }
#pragma unroll
            for (int mt = 0; mt < 4; ++mt)
#pragma unroll
                for (int q = 0; q < 2; ++q) {
                    MMA16816(acc[mt][half * 4 + 2 * q],     al[mt], bh[q][0], bh[q][1]);
                    MMA16816(acc[mt][half * 4 + 2 * q + 1], al[mt], bh[q][2], bh[q][3]);
                }
        }

        if (it + 3 < NIT) issue(it + 3);
        else CPA_COMMIT();
    }

    const int rowb = mtile * BM + rm + (lane >> 2);
    const int colb = ntile * BN + nb + (lane & 3) * 2;
#pragma unroll
    for (int mt = 0; mt < 4; ++mt) {
#pragma unroll
        for (int nt = 0; nt < 8; ++nt) {
            float* p = C + (size_t)(rowb + mt * 16) * N + colb + nt * 8;
            *(float2*)p                   = make_float2(acc[mt][nt][0], acc[mt][nt][1]);
            *(float2*)(p + 8 * (size_t)N) = make_float2(acc[mt][nt][2], acc[mt][nt][3]);
        }
    }
}

// ============================================================================
// Window attention: one block per (head, window), 128 threads.
// Score & AV phases use packed fma.rn.f32x2 (FFMA2).
// Output written directly as bf16 hi/lo.
// ============================================================================
__global__ __launch_bounds__(128) void window_attn_kernel(
    const float* __restrict__ qkv,
    uint16_t* __restrict__ atthi, uint16_t* __restrict__ attlo)
{
    __shared__ __align__(16) float Qs[L * 68];
    __shared__ __align__(16) float Ks[L * 68];
    __shared__ __align__(16) float Vs[L * 64];
    __shared__ float S[L * 52];
    __shared__ float qn[L], kn[L];
    __shared__ int grows[L];

    const int h   = blockIdx.x;
    const int w   = blockIdx.y;
    const int tid = threadIdx.x;
    const int lane = tid & 31;
    const int warp = tid >> 5;
    const int b   = w >> 10;
    const int rem = w & 1023;
    const int wh  = rem >> 5, ww = rem & 31;

    if (tid < L) {
        int ty = tid / WS, tx = tid - ty * WS;
        int y = wh * WS + ty + SHIFT; if (y >= IMG) y -= IMG;
        int x = ww * WS + tx + SHIFT; if (x >= IMG) x -= IMG;
        grows[tid] = b * (IMG * IMG) + y * IMG + x;
    }
    __syncthreads();

    // ---- load phase: q/k rows (RoPE) + v rows, all 4 warps ----
    for (int r = warp; r < 3 * L; r += 4) {
        int kind = r / L;
        int row  = r - kind * L;
        size_t base = (size_t)grows[row] * (3 * DIM) + h * HD + (size_t)kind * DIM;
        float t1 = qkv[base + lane];
        float t2 = qkv[base + lane + 32];
        if (kind == 2) {
            Vs[row * 64 + lane]      = t1;
            Vs[row * 64 + lane + 32] = t2;
        } else {
            float s = g_sin[row * 32 + lane];
            float c = g_cos[row * 32 + lane];
            float r1 = t1 * c - t2 * s;
            float r2 = t1 * s + t2 * c;
            float* dst = (kind == 0) ? Qs : Ks;
            dst[row * 68 + lane]      = r1;
            dst[row * 68 + lane + 32] = r2;
        }
    }
    __syncthreads();

    // ---- norms ----
    if (tid < L) {
        float ssq = 0.0f;
#pragma unroll
        for (int d4 = 0; d4 < 16; ++d4) {
            float4 v = *(const float4*)&Ks[tid * 68 + d4 * 4];
            ssq += v.x * v.x + v.y * v.y + v.z * v.z + v.w * v.w;
        }
        kn[tid] = 1.0f / fmaxf(sqrtf(ssq), 1e-12f);
    } else if (tid >= 64 && tid < 64 + L) {
        int i = tid - 64;
        float ssq = 0.0f;
#pragma unroll
        for (int d4 = 0; d4 < 16; ++d4) {
            float4 v = *(const float4*)&Qs[i * 68 + d4 * 4];
            ssq += v.x * v.x + v.y * v.y + v.z * v.z + v.w * v.w;
        }
        qn[i] = 100.0f / fmaxf(sqrtf(ssq), 1e-12f);
    }
    __syncthreads();

    // ---- scores: 98 threads, packed f32x2 dot products ----
    if (tid < 2 * L) {
        int g = (tid >= L) ? 1 : 0;
        int i = tid - g * L;
        unsigned long long qp[32];
#pragma unroll
        for (int d4 = 0; d4 < 16; ++d4) {
            float4 v = *(const float4*)&Qs[i * 68 + d4 * 4];
            qp[d4 * 2]     = pk2(v.x, v.y);
            qp[d4 * 2 + 1] = pk2(v.z, v.w);
        }
        float qs = qn[i];
        int j0 = g ? 25 : 0, j1 = g ? L : 25;
        for (int j = j0; j < j1; ++j) {
            unsigned long long a0 = 0, a1 = 0, a2 = 0, a3 = 0;
#pragma unroll
            for (int d4 = 0; d4 < 8; ++d4) {
                float4 k0 = *(const float4*)&Ks[j * 68 + d4 * 8];
                float4 k1 = *(const float4*)&Ks[j * 68 + d4 * 8 + 4];
                fma2(a0, qp[d4 * 4],     pk2(k0.x, k0.y));
                fma2(a1, qp[d4 * 4 + 1], pk2(k0.z, k0.w));
                fma2(a2, qp[d4 * 4 + 2], pk2(k1.x, k1.y));
                fma2(a3, qp[d4 * 4 + 3], pk2(k1.z, k1.w));
            }
            float2 r0 = upk2(a0), r1 = upk2(a1), r2 = upk2(a2), r3 = upk2(a3);
            float dot = (r0.x + r0.y) + (r1.x + r1.y) + (r2.x + r2.y) + (r3.x + r3.y);
            S[i * 52 + j] = dot * (qs * kn[j]);
        }
    }
    __syncthreads();

    // ---- softmax per row ----
    if (tid < L) {
        float mx = -1e30f;
        for (int j = 0; j < L; ++j) mx = fmaxf(mx, S[tid * 52 + j]);
        float sum = 0.0f;
        for (int j = 0; j < L; ++j) {
            float e = __expf(S[tid * 52 + j] - mx);
            S[tid * 52 + j] = e;
            sum += e;
        }
        float inv = 1.0f / sum;
        for (int j = 0; j < L; ++j) S[tid * 52 + j] *= inv;
    }
    __syncthreads();

    // ---- AV: 98 threads, packed f32x2 accumulation ----
    if (tid < 2 * L) {
        int g = (tid >= L) ? 1 : 0;
        int i = tid - g * L;
        unsigned long long ov[16];
#pragma unroll
        for (int d = 0; d < 16; ++d) ov[d] = 0ull;
        for (int j = 0; j < L; ++j) {
            float wgt = S[i * 52 + j];
            unsigned long long wp = pk2(wgt, wgt);
#pragma unroll
            for (int d4 = 0; d4 < 4; ++d4) {
                float4 v0 = *(const float4*)&Vs[j * 64 + g * 32 + d4 * 8];
                float4 v1 = *(const float4*)&Vs[j * 64 + g * 32 + d4 * 8 + 4];
                fma2(ov[d4 * 4],     wp, pk2(v0.x, v0.y));
                fma2(ov[d4 * 4 + 1], wp, pk2(v0.z, v0.w));
                fma2(ov[d4 * 4 + 2], wp, pk2(v1.x, v1.y));
                fma2(ov[d4 * 4 + 3], wp, pk2(v1.z, v1.w));
            }
        }
#pragma unroll
        for (int d = 0; d < 16; ++d) {
            float2 r = upk2(ov[d]);
            Qs[i * 68 + g * 32 + d * 2]     = r.x;
            Qs[i * 68 + g * 32 + d * 2 + 1] = r.y;
        }
    }
    __syncthreads();

    // ---- scatter store as bf16 hi/lo ----
    for (int t = warp; t < L; t += 4) {
        size_t o = (size_t)grows[t] * DIM + h * HD;
        float v0 = Qs[t * 68 + lane];
        float v1 = Qs[t * 68 + lane + 32];
        uint16_t h0, l0, h1, l1;
        split1(v0, h0, l0);
        split1(v1, h1, l1);
        atthi[o + lane]      = h0;
        attlo[o + lane]      = l0;
        atthi[o + lane + 32] = h1;
        attlo[o + lane + 32] = l1;
    }
}

// ---------------------------------------------------------------------------
extern "C" void kernel_launch(void* const* d_in, const int* in_sizes, int n_in,
                              void* d_out, int out_size)
{
    const float* x     = (const float*)d_in[0];
    const float* qkv_w = (const float*)d_in[1];
    const float* projw = (const float*)d_in[2];
    float* out = (float*)d_out;

    float *qkv_ptr;
    uint16_t *xhi, *xlo, *qwhi, *qwlo, *pwhi, *pwlo, *atthi, *attlo;
    cudaGetSymbolAddress((void**)&qkv_ptr, g_qkv);
    cudaGetSymbolAddress((void**)&xhi,  g_xhi);
    cudaGetSymbolAddress((void**)&xlo,  g_xlo);
    cudaGetSymbolAddress((void**)&qwhi, g_qwhi);
    cudaGetSymbolAddress((void**)&qwlo, g_qwlo);
    cudaGetSymbolAddress((void**)&pwhi, g_pwhi);
    cudaGetSymbolAddress((void**)&pwlo, g_pwlo);
    cudaGetSymbolAddress((void**)&atthi, g_atthi);
    cudaGetSymbolAddress((void**)&attlo, g_attlo);

    cudaFuncSetAttribute(gemm_presplit_kernel,
                         cudaFuncAttributeMaxDynamicSharedMemorySize, SMEM_GEMM);

    // Launch order chosen so the qkv GEMM is launch #4 (the profiled slot).
    rope_init_kernel<<<1, 256>>>();                                            // 1
    split_kernel<<<1024, 256>>>(x,     xhi,  xlo,  (size_t)TOKENS * DIM / 4);  // 2
    split_kernel<<<64,   256>>>(qkv_w, qwhi, qwlo, (size_t)3 * DIM * DIM / 4); // 3

    // qkv = x @ qkv_w^T : M=100352, N=2304, K=768                              // 4
    gemm_presplit_kernel<<<dim3(3 * DIM / BN, TOKENS / BM), 256, SMEM_GEMM>>>(
        xhi, xlo, qwhi, qwlo, qkv_ptr, TOKENS, 3 * DIM, DIM);

    split_kernel<<<32,   256>>>(projw, pwhi, pwlo, (size_t)DIM * DIM / 4);     // 5

    // windowed attention (writes bf16 hi/lo att)                              // 6
    window_attn_kernel<<<dim3(NH, NWIN), 128>>>(qkv_ptr, atthi, attlo);

    // out = att @ proj_w^T : M=100352, N=768, K=768                            // 7
    gemm_presplit_kernel<<<dim3(DIM / BN, TOKENS / BM), 256, SMEM_GEMM>>>(
        atthi, attlo, pwhi, pwlo, out, TOKENS, DIM, DIM);
}

// round 8
// speedup vs baseline: 1.0387x; 1.0387x over previous
#include <cuda_runtime.h>
#include <math.h>
#include <stdint.h>

// Problem constants (fixed by setup_inputs)
#define BATCH   2
#define IMG     224
#define TOKENS  (BATCH*IMG*IMG)   // 100352
#define DIM     768
#define NH      12
#define HD      64
#define WS      7
#define L       (WS*WS)           // 49
#define NWIN    (BATCH*(IMG/WS)*(IMG/WS))  // 2048
#define SHIFT   3

// Scratch (device globals: allocation is forbidden in kernel_launch)
__device__ float    g_qkv[(size_t)TOKENS * 3 * DIM];
__device__ uint16_t g_xhi[(size_t)TOKENS * DIM];
__device__ uint16_t g_xlo[(size_t)TOKENS * DIM];
__device__ uint16_t g_qwhi[(size_t)3 * DIM * DIM];
__device__ uint16_t g_qwlo[(size_t)3 * DIM * DIM];
__device__ uint16_t g_pwhi[(size_t)DIM * DIM];
__device__ uint16_t g_pwlo[(size_t)DIM * DIM];
__device__ uint16_t g_atthi[(size_t)TOKENS * DIM];
__device__ uint16_t g_attlo[(size_t)TOKENS * DIM];
__device__ float    g_sin[L * 32];
__device__ float    g_cos[L * 32];

// ============================================================================
// helpers
// ============================================================================
__device__ __forceinline__ uint32_t smem_u32(const void* p) {
    uint32_t a;
    asm("{ .reg .u64 t; cvta.to.shared.u64 t, %1; cvt.u32.u64 %0, t; }" : "=r"(a) : "l"(p));
    return a;
}

__device__ __forceinline__ void split_pack(float x, float y, uint32_t& hi, uint32_t& lo) {
    asm("cvt.rn.bf16x2.f32 %0, %1, %2;" : "=r"(hi) : "f"(y), "f"(x));
    float hx = __uint_as_float(hi << 16);
    float hy = __uint_as_float(hi & 0xffff0000u);
    float lx = x - hx;
    float ly = y - hy;
    asm("cvt.rn.bf16x2.f32 %0, %1, %2;" : "=r"(lo) : "f"(ly), "f"(lx));
}

__device__ __forceinline__ void split1(float x, uint16_t& h, uint16_t& l) {
    uint16_t hh;
    asm("cvt.rn.bf16.f32 %0, %1;" : "=h"(hh) : "f"(x));
    float hf = __uint_as_float(((uint32_t)hh) << 16);
    asm("cvt.rn.bf16.f32 %0, %1;" : "=h"(l) : "f"(x - hf));
    h = hh;
}

// ---- packed f32x2 (Blackwell FFMA2) ----
__device__ __forceinline__ unsigned long long pk2(float x, float y) {
    unsigned long long r;
    asm("mov.b64 %0, {%1,%2};" : "=l"(r) : "f"(x), "f"(y));
    return r;
}
__device__ __forceinline__ void fma2(unsigned long long& d,
                                     unsigned long long a, unsigned long long b) {
    asm("fma.rn.f32x2 %0, %1, %2, %0;" : "+l"(d) : "l"(a), "l"(b));
}
__device__ __forceinline__ float2 upk2(unsigned long long v) {
    float x, y;
    asm("mov.b64 {%0,%1}, %2;" : "=f"(x), "=f"(y) : "l"(v));
    return make_float2(x, y);
}

#define CPA16(dst, src) \
    asm volatile("cp.async.cg.shared.global [%0], [%1], 16;" :: "r"(dst), "l"(src) : "memory")
#define CPA_COMMIT() asm volatile("cp.async.commit_group;" ::: "memory")
#define CPA_WAIT2()  asm volatile("cp.async.wait_group 2;" ::: "memory")

#define LDSM4(r, addr) \
    asm volatile("ldmatrix.sync.aligned.m8n8.x4.shared.b16 {%0,%1,%2,%3}, [%4];" \
        : "=r"((r)[0]), "=r"((r)[1]), "=r"((r)[2]), "=r"((r)[3]) : "r"(addr))

#define MMA16816(d, a, b0, b1) \
    asm volatile("mma.sync.aligned.m16n8k16.row.col.f32.bf16.bf16.f32 " \
        "{%0,%1,%2,%3},{%4,%5,%6,%7},{%8,%9},{%0,%1,%2,%3};" \
        : "+f"((d)[0]), "+f"((d)[1]), "+f"((d)[2]), "+f"((d)[3]) \
        : "r"((a)[0]), "r"((a)[1]), "r"((a)[2]), "r"((a)[3]), "r"(b0), "r"(b1))

// ============================================================================
// RoPE tables
// ============================================================================
__global__ void rope_init_kernel() {
    for (int i = threadIdx.x; i < L * 32; i += blockDim.x) {
        int tok = i >> 5, d = i & 31;
        int ty = tok / WS, tx = tok - ty * WS;
        int f = d & 15;
        float inv = powf(100.0f, -((float)f) / 16.0f);
        float ang = ((d < 16) ? (float)ty : (float)tx) * inv;
        g_sin[i] = sinf(ang);
        g_cos[i] = cosf(ang);
    }
}

// ============================================================================
// fp32 -> bf16 hi/lo split pre-pass
// ============================================================================
__global__ void split_kernel(const float* __restrict__ src,
                             uint16_t* __restrict__ hi, uint16_t* __restrict__ lo,
                             size_t n4)
{
    size_t idx = (size_t)blockIdx.x * blockDim.x + threadIdx.x;
    size_t stride = (size_t)gridDim.x * blockDim.x;
    for (; idx < n4; idx += stride) {
        float4 v = ((const float4*)src)[idx];
        uint32_t h0, l0, h1, l1;
        split_pack(v.x, v.y, h0, l0);
        split_pack(v.z, v.w, h1, l1);
        ((uint2*)hi)[idx] = make_uint2(h0, h1);
        ((uint2*)lo)[idx] = make_uint2(l0, l1);
    }
}

// ============================================================================
// 3x-BF16-split GEMM, 2 CTAs/SM:
//   C[M,N] = A[M,K] @ W[N,K]^T  (fp32 out)
// CTA tile 128x128, BK=16, 256 threads (8 warps, 4m x 2n, warp tile 32x64),
// cp.async 4-stage. Requires M%128==0, N%128==0, K%16==0.
// ============================================================================
#define BM 128
#define BN 128
#define BK 16
#define PADB 48
#define A_LO  6144u
#define B_HI  12288u
#define B_LO  18432u
#define BUF_B 24576u
#define STAGES 4
#define SMEM_GEMM (STAGES * BUF_B)   // 98304

__global__ __launch_bounds__(256, 2) void gemm_presplit_kernel(
    const uint16_t* __restrict__ Ahi, const uint16_t* __restrict__ Alo,
    const uint16_t* __restrict__ Bhi, const uint16_t* __restrict__ Blo,
    float* __restrict__ C, int M, int N, int K)
{
    extern __shared__ char smem[];
    const uint32_t sb = smem_u32(smem);
    const int tid  = threadIdx.x;
    const int lane = tid & 31;
    const int wid  = tid >> 5;
    const int mtile = blockIdx.y, ntile = blockIdx.x;
    const int rm = (wid & 3) * 32;    // 4 m-warps
    const int nb = (wid >> 2) * 64;   // 2 n-warps

    // cp.async: thread t handles row t>>1, 16B chunk t&1 of each tile version
    const int row = tid >> 1, half = tid & 1;
    const uint16_t* pAhi = Ahi + (size_t)(mtile * BM + row) * K + half * 8;
    const uint16_t* pAlo = Alo + (size_t)(mtile * BM + row) * K + half * 8;
    const uint16_t* pBhi = Bhi + (size_t)(ntile * BN + row) * K + half * 8;
    const uint16_t* pBlo = Blo + (size_t)(ntile * BN + row) * K + half * 8;

    const uint32_t dA = sb + (uint32_t)(row * PADB + half * 16);
    const uint32_t dB = sb + B_HI + (uint32_t)(row * PADB + half * 16);

    auto issue = [&](int s) {
        const uint32_t off = (uint32_t)(s & 3) * BUF_B;
        const int k0 = s * BK;
        CPA16(dA + off,                 pAhi + k0);
        CPA16(dA + off + A_LO,          pAlo + k0);
        CPA16(dB + off,                 pBhi + k0);
        CPA16(dB + off + (B_LO - B_HI), pBlo + k0);
        CPA_COMMIT();
    };

    float acc[2][8][4];
#pragma unroll
    for (int mt = 0; mt < 2; ++mt)
#pragma unroll
        for (int nt = 0; nt < 8; ++nt)
#pragma unroll
            for (int e = 0; e < 4; ++e) acc[mt][nt][e] = 0.0f;

    const uint32_t a_l = sb + (uint32_t)((rm + (lane & 15)) * PADB + (lane >> 4) * 16);
    const uint32_t b_l = sb + B_HI + (uint32_t)((nb + (lane & 7) + ((lane >> 4) << 3)) * PADB
                                                + ((lane >> 3) & 1) * 16);

    const int NIT = K / BK;   // 48
    issue(0); issue(1); issue(2);

    for (int it = 0; it < NIT; ++it) {
        CPA_WAIT2();
        __syncthreads();
        const uint32_t so = (uint32_t)(it & 3) * BUF_B;

        // A fragments: 2 x 16-row sub-tiles, hi+lo
        uint32_t ah[2][4], al[2][4];
#pragma unroll
        for (int mt = 0; mt < 2; ++mt) {
            LDSM4(ah[mt], a_l + so + mt * (16 * PADB));
            LDSM4(al[mt], a_l + so + A_LO + mt * (16 * PADB));
        }

#pragma unroll
        for (int hf = 0; hf < 2; ++hf) {
            uint32_t bh[2][4], bl[2][4];
#pragma unroll
            for (int q = 0; q < 2; ++q) {
                const int nt2 = hf * 2 + q;
                LDSM4(bh[q], b_l + so + nt2 * (16 * PADB));
                LDSM4(bl[q], b_l + so + (B_LO - B_HI) + nt2 * (16 * PADB));
            }
#pragma unroll
            for (int mt = 0; mt < 2; ++mt)
#pragma unroll
                for (int q = 0; q < 2; ++q) {
                    MMA16816(acc[mt][hf * 4 + 2 * q],     ah[mt], bh[q][0], bh[q][1]);
                    MMA16816(acc[mt][hf * 4 + 2 * q + 1], ah[mt], bh[q][2], bh[q][3]);
                }
#pragma unroll
            for (int mt = 0; mt < 2; ++mt)
#pragma unroll
                for (int q = 0; q < 2; ++q) {
                    MMA16816(acc[mt][hf * 4 + 2 * q],     ah[mt], bl[q][0], bl[q][1]);
                    MMA16816(acc[mt][hf * 4 + 2 * q + 1], ah[mt], bl[q][2], bl[q][3]);
                }
#pragma unroll
            for (int mt = 0; mt < 2; ++mt)
#pragma unroll
                for (int q = 0; q < 2; ++q) {
                    MMA16816(acc[mt][hf * 4 + 2 * q],     al[mt], bh[q][0], bh[q][1]);
                    MMA16816(acc[mt][hf * 4 + 2 * q + 1], al[mt], bh[q][2], bh[q][3]);
                }
        }

        if (it + 3 < NIT) issue(it + 3);
        else CPA_COMMIT();   // empty group keeps wait count uniform
    }

    // ---- epilogue ----
    const int rowb = mtile * BM + rm + (lane >> 2);
    const int colb = ntile * BN + nb + (lane & 3) * 2;
#pragma unroll
    for (int mt = 0; mt < 2; ++mt) {
#pragma unroll
        for (int nt = 0; nt < 8; ++nt) {
            float* p = C + (size_t)(rowb + mt * 16) * N + colb + nt * 8;
            *(float2*)p                   = make_float2(acc[mt][nt][0], acc[mt][nt][1]);
            *(float2*)(p + 8 * (size_t)N) = make_float2(acc[mt][nt][2], acc[mt][nt][3]);
        }
    }
}

// ============================================================================
// Window attention: one block per (head, window), 128 threads.
// ============================================================================
__global__ __launch_bounds__(128) void window_attn_kernel(
    const float* __restrict__ qkv,
    uint16_t* __restrict__ atthi, uint16_t* __restrict__ attlo)
{
    __shared__ __align__(16) float Qs[L * 68];
    __shared__ __align__(16) float Ks[L * 68];
    __shared__ __align__(16) float Vs[L * 64];
    __shared__ float S[L * 52];
    __shared__ float qn[L], kn[L];
    __shared__ int grows[L];

    const int h   = blockIdx.x;
    const int w   = blockIdx.y;
    const int tid = threadIdx.x;
    const int lane = tid & 31;
    const int warp = tid >> 5;
    const int b   = w >> 10;
    const int rem = w & 1023;
    const int wh  = rem >> 5, ww = rem & 31;

    if (tid < L) {
        int ty = tid / WS, tx = tid - ty * WS;
        int y = wh * WS + ty + SHIFT; if (y >= IMG) y -= IMG;
        int x = ww * WS + tx + SHIFT; if (x >= IMG) x -= IMG;
        grows[tid] = b * (IMG * IMG) + y * IMG + x;
    }
    __syncthreads();

    for (int r = warp; r < 3 * L; r += 4) {
        int kind = r / L;
        int rw   = r - kind * L;
        size_t base = (size_t)grows[rw] * (3 * DIM) + h * HD + (size_t)kind * DIM;
        float t1 = qkv[base + lane];
        float t2 = qkv[base + lane + 32];
        if (kind == 2) {
            Vs[rw * 64 + lane]      = t1;
            Vs[rw * 64 + lane + 32] = t2;
        } else {
            float s = g_sin[rw * 32 + lane];
            float c = g_cos[rw * 32 + lane];
            float r1 = t1 * c - t2 * s;
            float r2 = t1 * s + t2 * c;
            float* dst = (kind == 0) ? Qs : Ks;
            dst[rw * 68 + lane]      = r1;
            dst[rw * 68 + lane + 32] = r2;
        }
    }
    __syncthreads();

    if (tid < L) {
        float ssq = 0.0f;
#pragma unroll
        for (int d4 = 0; d4 < 16; ++d4) {
            float4 v = *(const float4*)&Ks[tid * 68 + d4 * 4];
            ssq += v.x * v.x + v.y * v.y + v.z * v.z + v.w * v.w;
        }
        kn[tid] = 1.0f / fmaxf(sqrtf(ssq), 1e-12f);
    } else if (tid >= 64 && tid < 64 + L) {
        int i = tid - 64;
        float ssq = 0.0f;
#pragma unroll
        for (int d4 = 0; d4 < 16; ++d4) {
            float4 v = *(const float4*)&Qs[i * 68 + d4 * 4];
            ssq += v.x * v.x + v.y * v.y + v.z * v.z + v.w * v.w;
        }
        qn[i] = 100.0f / fmaxf(sqrtf(ssq), 1e-12f);
    }
    __syncthreads();

    if (tid < 2 * L) {
        int g = (tid >= L) ? 1 : 0;
        int i = tid - g * L;
        unsigned long long qp[32];
#pragma unroll
        for (int d4 = 0; d4 < 16; ++d4) {
            float4 v = *(const float4*)&Qs[i * 68 + d4 * 4];
            qp[d4 * 2]     = pk2(v.x, v.y);
            qp[d4 * 2 + 1] = pk2(v.z, v.w);
        }
        float qs = qn[i];
        int j0 = g ? 25 : 0, j1 = g ? L : 25;
        for (int j = j0; j < j1; ++j) {
            unsigned long long a0 = 0, a1 = 0, a2 = 0, a3 = 0;
#pragma unroll
            for (int d4 = 0; d4 < 8; ++d4) {
                float4 k0 = *(const float4*)&Ks[j * 68 + d4 * 8];
                float4 k1 = *(const float4*)&Ks[j * 68 + d4 * 8 + 4];
                fma2(a0, qp[d4 * 4],     pk2(k0.x, k0.y));
                fma2(a1, qp[d4 * 4 + 1], pk2(k0.z, k0.w));
                fma2(a2, qp[d4 * 4 + 2], pk2(k1.x, k1.y));
                fma2(a3, qp[d4 * 4 + 3], pk2(k1.z, k1.w));
            }
            float2 r0 = upk2(a0), r1 = upk2(a1), r2 = upk2(a2), r3 = upk2(a3);
            float dot = (r0.x + r0.y) + (r1.x + r1.y) + (r2.x + r2.y) + (r3.x + r3.y);
            S[i * 52 + j] = dot * (qs * kn[j]);
        }
    }
    __syncthreads();

    if (tid < L) {
        float mx = -1e30f;
        for (int j = 0; j < L; ++j) mx = fmaxf(mx, S[tid * 52 + j]);
        float sum = 0.0f;
        for (int j = 0; j < L; ++j) {
            float e = __expf(S[tid * 52 + j] - mx);
            S[tid * 52 + j] = e;
            sum += e;
        }
        float inv = 1.0f / sum;
        for (int j = 0; j < L; ++j) S[tid * 52 + j] *= inv;
    }
    __syncthreads();

    if (tid < 2 * L) {
        int g = (tid >= L) ? 1 : 0;
        int i = tid - g * L;
        unsigned long long ov[16];
#pragma unroll
        for (int d = 0; d < 16; ++d) ov[d] = 0ull;
        for (int j = 0; j < L; ++j) {
            float wgt = S[i * 52 + j];
            unsigned long long wp = pk2(wgt, wgt);
#pragma unroll
            for (int d4 = 0; d4 < 4; ++d4) {
                float4 v0 = *(const float4*)&Vs[j * 64 + g * 32 + d4 * 8];
                float4 v1 = *(const float4*)&Vs[j * 64 + g * 32 + d4 * 8 + 4];
                fma2(ov[d4 * 4],     wp, pk2(v0.x, v0.y));
                fma2(ov[d4 * 4 + 1], wp, pk2(v0.z, v0.w));
                fma2(ov[d4 * 4 + 2], wp, pk2(v1.x, v1.y));
                fma2(ov[d4 * 4 + 3], wp, pk2(v1.z, v1.w));
            }
        }
#pragma unroll
        for (int d = 0; d < 16; ++d) {
            float2 r = upk2(ov[d]);
            Qs[i * 68 + g * 32 + d * 2]     = r.x;
            Qs[i * 68 + g * 32 + d * 2 + 1] = r.y;
        }
    }
    __syncthreads();

    for (int t = warp; t < L; t += 4) {
        size_t o = (size_t)grows[t] * DIM + h * HD;
        float v0 = Qs[t * 68 + lane];
        float v1 = Qs[t * 68 + lane + 32];
        uint16_t h0, l0, h1, l1;
        split1(v0, h0, l0);
        split1(v1, h1, l1);
        atthi[o + lane]      = h0;
        attlo[o + lane]      = l0;
        atthi[o + lane + 32] = h1;
        attlo[o + lane + 32] = l1;
    }
}

// ---------------------------------------------------------------------------
extern "C" void kernel_launch(void* const* d_in, const int* in_sizes, int n_in,
                              void* d_out, int out_size)
{
    const float* x     = (const float*)d_in[0];
    const float* qkv_w = (const float*)d_in[1];
    const float* projw = (const float*)d_in[2];
    float* out = (float*)d_out;

    float *qkv_ptr;
    uint16_t *xhi, *xlo, *qwhi, *qwlo, *pwhi, *pwlo, *atthi, *attlo;
    cudaGetSymbolAddress((void**)&qkv_ptr, g_qkv);
    cudaGetSymbolAddress((void**)&xhi,  g_xhi);
    cudaGetSymbolAddress((void**)&xlo,  g_xlo);
    cudaGetSymbolAddress((void**)&qwhi, g_qwhi);
    cudaGetSymbolAddress((void**)&qwlo, g_qwlo);
    cudaGetSymbolAddress((void**)&pwhi, g_pwhi);
    cudaGetSymbolAddress((void**)&pwlo, g_pwlo);
    cudaGetSymbolAddress((void**)&atthi, g_atthi);
    cudaGetSymbolAddress((void**)&attlo, g_attlo);

    cudaFuncSetAttribute(gemm_presplit_kernel,
                         cudaFuncAttributeMaxDynamicSharedMemorySize, SMEM_GEMM);

    // qkv GEMM kept as launch #4 (the profiled slot).
    rope_init_kernel<<<1, 256>>>();                                            // 1
    split_kernel<<<1024, 256>>>(x,     xhi,  xlo,  (size_t)TOKENS * DIM / 4);  // 2
    split_kernel<<<64,   256>>>(qkv_w, qwhi, qwlo, (size_t)3 * DIM * DIM / 4); // 3

    // qkv = x @ qkv_w^T : M=100352, N=2304, K=768                              // 4
    gemm_presplit_kernel<<<dim3(3 * DIM / BN, TOKENS / BM), 256, SMEM_GEMM>>>(
        xhi, xlo, qwhi, qwlo, qkv_ptr, TOKENS, 3 * DIM, DIM);

    split_kernel<<<32,   256>>>(projw, pwhi, pwlo, (size_t)DIM * DIM / 4);     // 5

    // windowed attention (writes bf16 hi/lo att)                              // 6
    window_attn_kernel<<<dim3(NH, NWIN), 128>>>(qkv_ptr, atthi, attlo);

    // out = att @ proj_w^T : M=100352, N=768, K=768                            // 7
    gemm_presplit_kernel<<<dim3(DIM / BN, TOKENS / BM), 256, SMEM_GEMM>>>(
        atthi, attlo, pwhi, pwlo, out, TOKENS, DIM, DIM);
}